// round 11
// baseline (speedup 1.0000x reference)
#include <cuda_runtime.h>
#include <math_constants.h>

#define DD   128
#define HH   4
#define RNUM 2000
#define MAXM 768
#define NCPY 32
#define XST  132
#define CH   32

// ---------------- scratch ----------------
__device__ float  g_a[HH * DD];
__device__ float  g_c[HH];
__device__ float  g_qf[DD];
__device__ int    g_cnt32[NCPY * RNUM];   // invariant: zero at entry (scan resets)
__device__ int    g_cur32[NCPY * RNUM];
__device__ int    g_deg[RNUM];            // invariant: zero at entry (scan resets)
__device__ int    g_starts[RNUM + 1];
__device__ float  g_dis[RNUM];
__device__ int    g_idx[1 << 20];
__device__ float  g_Px[RNUM * HH * DD];
__device__ float  g_hg[RNUM * DD];

// ---------------- launch 1: qf (block 0) + hist/deg (rest) ----------------
__global__ void k_hist(const float* __restrict__ S, const float* __restrict__ Wq,
                       const float* __restrict__ bq,
                       const int* __restrict__ zone, int N,
                       const int* __restrict__ edst, int E) {
    int t = threadIdx.x;
    if (blockIdx.x == 0) {
        __shared__ float sS[DD];
        if (t < DD) sS[t] = S[t];
        __syncthreads();
        if (t < DD) {
            const float4* wr = (const float4*)(Wq + t * DD);
            const float4* sv = (const float4*)sS;
            float s = 0.f;
#pragma unroll
            for (int j = 0; j < 32; j++) {
                float4 w = wr[j], v = sv[j];
                s += w.x * v.x + w.y * v.y + w.z * v.z + w.w * v.w;
            }
            g_qf[t] = s + bq[t];
        }
        return;
    }
    int i = (blockIdx.x - 1) * 256 + t;
    if (i < N) {
        int c = (i >> 8) & (NCPY - 1);
        atomicAdd(&g_cnt32[c * RNUM + zone[i]], 1);
    }
    if (i < E) atomicAdd(&g_deg[edst[i]], 1);
}

// ---------------- launch 2: block 0 = scan; blocks 1-4 = a/c per head ----------------
__global__ void k_scan(const float* __restrict__ Wk, const float* __restrict__ bk) {
    int t = threadIdx.x; // 1024
    if (blockIdx.x > 0) {
        int h = blockIdx.x - 1;
        __shared__ float sq[32];
        __shared__ float spart[8 * DD];
        if (t < 32) sq[t] = g_qf[h * 32 + t];
        __syncthreads();
        const float scale = 0.08838834764831845f; // 1/sqrt(128)
        int j = t & 127, part = t >> 7;
        float acc = 0.f;
#pragma unroll
        for (int k = 0; k < 4; k++) {
            int dh = part * 4 + k;
            acc += sq[dh] * Wk[(h * 32 + dh) * DD + j];
        }
        spart[part * DD + j] = acc;
        __syncthreads();
        if (t < DD) {
            float s = 0.f;
#pragma unroll
            for (int p = 0; p < 8; p++) s += spart[p * DD + t];
            g_a[h * DD + t] = s * scale;
        }
        if (t == 128) {
            float s = 0.f;
#pragma unroll
            for (int dh = 0; dh < 32; dh++) s += sq[dh] * bk[h * 32 + dh];
            g_c[h] = s * scale;
        }
        return;
    }
    __shared__ int sbuf[2][2048];
    for (int k = 0; k < 2; k++) {
        int r = t + k * 1024;
        int tot = 0;
        if (r < RNUM)
            for (int c = 0; c < NCPY; c++) tot += g_cnt32[c * RNUM + r];
        sbuf[0][r] = tot;
    }
    __syncthreads();
    int src = 0;
    for (int off = 1; off < 2048; off <<= 1) {
        for (int k = 0; k < 2; k++) {
            int i = t + k * 1024;
            int v = sbuf[src][i];
            if (i >= off) v += sbuf[src][i - off];
            sbuf[1 - src][i] = v;
        }
        __syncthreads();
        src ^= 1;
    }
    for (int k = 0; k < 2; k++) {
        int r = t + k * 1024;
        if (r <= RNUM) g_starts[r] = (r == 0) ? 0 : sbuf[src][r - 1];
        if (r < RNUM) {
            int run = (r == 0) ? 0 : sbuf[src][r - 1];
            for (int c = 0; c < NCPY; c++) {
                int v = g_cnt32[c * RNUM + r];
                g_cur32[c * RNUM + r] = run;
                run += v;
                g_cnt32[c * RNUM + r] = 0;
            }
            g_dis[r] = rsqrtf((float)(g_deg[r] + 1));
            g_deg[r] = 0;
        }
    }
}

// ---------------- launch 3: scatter ----------------
__global__ void k_scatter(const int* __restrict__ zone, int N) {
    int i = blockIdx.x * blockDim.x + threadIdx.x;
    if (i < N) {
        int z = zone[i];
        int c = (i >> 8) & (NCPY - 1);
        int pos = atomicAdd(&g_cur32[c * RNUM + z], 1);
        g_idx[pos] = i;
    }
}

// ---------------- launch 4: region — two-phase chunked, shuffle-free ----------------
__device__ __forceinline__ void cp16(void* dst_smem, const void* src_gmem) {
    unsigned d = (unsigned)__cvta_generic_to_shared(dst_smem);
    asm volatile("cp.async.ca.shared.global [%0], [%1], 16;\n" :: "r"(d), "l"(src_gmem));
}
__device__ __forceinline__ void cp_commit() {
    asm volatile("cp.async.commit_group;\n" ::: "memory");
}
__device__ __forceinline__ void cp_wait0() {
    asm volatile("cp.async.wait_group 0;\n" ::: "memory");
}

__global__ __launch_bounds__(256, 5) void k_region(const float* __restrict__ x) {
    int r = blockIdx.x;
    int base = g_starts[r];
    int cnt = g_starts[r + 1] - base;
    if (cnt > MAXM) cnt = MAXM;
    int t = threadIdx.x;

    if (cnt == 0) {
        for (int o = t; o < HH * DD; o += 256) g_Px[r * (HH * DD) + o] = 0.f;
        return;
    }

    __shared__ __align__(16) float pool[2][CH * XST];  // 33.8 KB; red aliases pool[0] at end
    __shared__ __align__(16) float saP[HH * XST];      // padded A (2.1 KB)
    __shared__ __align__(16) float se[CH * HH];        // exp-scores (0.5 KB)
    __shared__ int   sidx[MAXM];                       // 3 KB
    __shared__ float scc[HH];
    __shared__ float sden[8 * HH];
    __shared__ float sinv[HH];

    for (int i = t; i < HH * DD; i += 256) saP[(i >> 7) * XST + (i & 127)] = g_a[i];
    if (t < HH) scc[t] = g_c[t];
    for (int i = t; i < cnt; i += 256) sidx[i] = g_idx[base + i];
    __syncthreads();

    int warp = t >> 5, lane = t & 31;
    int nch = (cnt + CH - 1) / CH;

    // staging map: row = t>>3 (32 rows), part = t&7 (64B each), 4 x cp16
    int srow = t >> 3, spart = t & 7;

    // prologue: stage chunk 0
    {
        int cc = min(CH, cnt);
        if (srow < cc) {
            int n = sidx[srow];
            const float* src = x + (size_t)n * DD + spart * 16;
            float* dst = &pool[0][srow * XST + spart * 16];
#pragma unroll
            for (int q = 0; q < 4; q++) cp16(dst + q * 4, src + q * 4);
        }
        cp_commit();
    }

    int m = t >> 2, h = t & 3;          // phase A mapping
    float ch_c = scc[h];

    float4 acc0 = make_float4(0.f, 0.f, 0.f, 0.f), acc1 = acc0, acc2 = acc0, acc3 = acc0;
    float den0 = 0.f, den1 = 0.f, den2 = 0.f, den3 = 0.f;

    for (int c = 0; c < nch; c++) {
        int buf = c & 1;
        int cc = min(CH, cnt - c * CH);
        cp_wait0();
        __syncthreads();   // chunk c ready; phase B(c-1) complete everywhere

        // issue staging for chunk c+1 into the other buffer
        if (c + 1 < nch) {
            int cc1 = min(CH, cnt - (c + 1) * CH);
            if (srow < cc1) {
                int n = sidx[(c + 1) * CH + srow];
                const float* src = x + (size_t)n * DD + spart * 16;
                float* dst = &pool[buf ^ 1][srow * XST + spart * 16];
#pragma unroll
                for (int q = 0; q < 4; q++) cp16(dst + q * 4, src + q * 4);
            }
        }
        cp_commit();

        // ---- phase A: scores, thread = (member m, head h) ----
        if (m < cc) {
            const float4* xr = (const float4*)(pool[buf] + m * XST);
            const float4* ar = (const float4*)(saP + h * XST);
            float s = 0.f;
#pragma unroll 8
            for (int j = 0; j < 32; j++) {
                float4 xv = xr[j], av = ar[j];
                s += xv.x * av.x + xv.y * av.y + xv.z * av.z + xv.w * av.w;
            }
            se[m * HH + h] = __expf(s + ch_c);
        }
        __syncthreads();

        // ---- phase B: accumulate, warp-per-member-stride ----
        for (int i = warp; i < cc; i += 8) {
            float4 ev = *(const float4*)(se + i * HH);                 // broadcast
            float4 xv = *(const float4*)(pool[buf] + i * XST + lane * 4);
            acc0.x += ev.x * xv.x; acc0.y += ev.x * xv.y; acc0.z += ev.x * xv.z; acc0.w += ev.x * xv.w;
            acc1.x += ev.y * xv.x; acc1.y += ev.y * xv.y; acc1.z += ev.y * xv.z; acc1.w += ev.y * xv.w;
            acc2.x += ev.z * xv.x; acc2.y += ev.z * xv.y; acc2.z += ev.z * xv.z; acc2.w += ev.z * xv.w;
            acc3.x += ev.w * xv.x; acc3.y += ev.w * xv.y; acc3.z += ev.w * xv.z; acc3.w += ev.w * xv.w;
            den0 += ev.x; den1 += ev.y; den2 += ev.z; den3 += ev.w;
        }
    }
    __syncthreads();   // all phase B done; pool now dead -> alias as reduction buffer

    float* red = pool[0];   // 8 * HH * DD = 16 KB <= 16.9 KB
    ((float4*)(red + (warp * HH + 0) * DD))[lane] = acc0;
    ((float4*)(red + (warp * HH + 1) * DD))[lane] = acc1;
    ((float4*)(red + (warp * HH + 2) * DD))[lane] = acc2;
    ((float4*)(red + (warp * HH + 3) * DD))[lane] = acc3;
    if (lane == 0) {
        sden[warp * HH + 0] = den0; sden[warp * HH + 1] = den1;
        sden[warp * HH + 2] = den2; sden[warp * HH + 3] = den3;
    }
    __syncthreads();
    if (t < HH) {
        float s = 0.f;
#pragma unroll
        for (int g = 0; g < 8; g++) s += sden[g * HH + t];
        sinv[t] = 1.f / s;
    }
    __syncthreads();
    for (int o = t; o < HH * DD; o += 256) {
        int hh = o >> 7, d = o & 127;
        float s = 0.f;
#pragma unroll
        for (int g = 0; g < 8; g++) s += red[(g * HH + hh) * DD + d];
        g_Px[r * (HH * DD) + o] = s * sinv[hh];
    }
}

// ---------------- launch 5: fused dense epilogue ----------------
__global__ __launch_bounds__(512) void k_epi(
    const float* __restrict__ Wv, const float* __restrict__ bv,
    const float* __restrict__ Wo, const float* __restrict__ bo,
    const float* __restrict__ Wg, const float* __restrict__ bg,
    float* __restrict__ out) {
    int rb = blockIdx.x * 16;
    __shared__ __align__(16) float sPx[16 * 512];
    __shared__ __align__(16) float sA[16 * XST];
    __shared__ __align__(16) float sB[16 * XST];
    __shared__ float sqf[DD];
    __shared__ float sflag[16];
    int t = threadIdx.x;

    for (int i = t; i < 16 * 512; i += 512) sPx[i] = g_Px[rb * 512 + i];
    if (t < DD) sqf[t] = g_qf[t];
    if (t < 16) sflag[t] = (g_starts[rb + t + 1] > g_starts[rb + t]) ? 1.f : 0.f;
    __syncthreads();

    int d = t & 127, rg = t >> 7;
    int h = d >> 5;
    {
        const float4* wv4 = (const float4*)(Wv + d * DD);
        float o0 = 0.f, o1 = 0.f, o2 = 0.f, o3 = 0.f;
#pragma unroll 8
        for (int j = 0; j < 32; j++) {
            float4 w = wv4[j];
            float4 p0 = ((const float4*)(sPx + (rg * 4 + 0) * 512 + h * DD))[j];
            float4 p1 = ((const float4*)(sPx + (rg * 4 + 1) * 512 + h * DD))[j];
            float4 p2 = ((const float4*)(sPx + (rg * 4 + 2) * 512 + h * DD))[j];
            float4 p3 = ((const float4*)(sPx + (rg * 4 + 3) * 512 + h * DD))[j];
            o0 += w.x * p0.x + w.y * p0.y + w.z * p0.z + w.w * p0.w;
            o1 += w.x * p1.x + w.y * p1.y + w.z * p1.z + w.w * p1.w;
            o2 += w.x * p2.x + w.y * p2.y + w.z * p2.z + w.w * p2.w;
            o3 += w.x * p3.x + w.y * p3.y + w.z * p3.z + w.w * p3.w;
        }
        float bvd = bv[d], qfd = sqf[d];
        sA[(rg * 4 + 0) * XST + d] = qfd + (o0 + bvd) * sflag[rg * 4 + 0];
        sA[(rg * 4 + 1) * XST + d] = qfd + (o1 + bvd) * sflag[rg * 4 + 1];
        sA[(rg * 4 + 2) * XST + d] = qfd + (o2 + bvd) * sflag[rg * 4 + 2];
        sA[(rg * 4 + 3) * XST + d] = qfd + (o3 + bvd) * sflag[rg * 4 + 3];
    }
    __syncthreads();
    {
        const float4* wo4 = (const float4*)(Wo + d * DD);
        float o0 = 0.f, o1 = 0.f, o2 = 0.f, o3 = 0.f;
#pragma unroll 8
        for (int j = 0; j < 32; j++) {
            float4 w = wo4[j];
            float4 p0 = ((const float4*)(sA + (rg * 4 + 0) * XST))[j];
            float4 p1 = ((const float4*)(sA + (rg * 4 + 1) * XST))[j];
            float4 p2 = ((const float4*)(sA + (rg * 4 + 2) * XST))[j];
            float4 p3 = ((const float4*)(sA + (rg * 4 + 3) * XST))[j];
            o0 += w.x * p0.x + w.y * p0.y + w.z * p0.z + w.w * p0.w;
            o1 += w.x * p1.x + w.y * p1.y + w.z * p1.z + w.w * p1.w;
            o2 += w.x * p2.x + w.y * p2.y + w.z * p2.z + w.w * p2.w;
            o3 += w.x * p3.x + w.y * p3.y + w.z * p3.z + w.w * p3.w;
        }
        float bod = bo[d];
        sB[(rg * 4 + 0) * XST + d] = sA[(rg * 4 + 0) * XST + d] + fmaxf(o0 + bod, 0.f);
        sB[(rg * 4 + 1) * XST + d] = sA[(rg * 4 + 1) * XST + d] + fmaxf(o1 + bod, 0.f);
        sB[(rg * 4 + 2) * XST + d] = sA[(rg * 4 + 2) * XST + d] + fmaxf(o2 + bod, 0.f);
        sB[(rg * 4 + 3) * XST + d] = sA[(rg * 4 + 3) * XST + d] + fmaxf(o3 + bod, 0.f);
    }
    __syncthreads();
    {
        const float4* wg4 = (const float4*)(Wg + d * DD);
        float o0 = 0.f, o1 = 0.f, o2 = 0.f, o3 = 0.f;
#pragma unroll 8
        for (int j = 0; j < 32; j++) {
            float4 w = wg4[j];
            float4 p0 = ((const float4*)(sB + (rg * 4 + 0) * XST))[j];
            float4 p1 = ((const float4*)(sB + (rg * 4 + 1) * XST))[j];
            float4 p2 = ((const float4*)(sB + (rg * 4 + 2) * XST))[j];
            float4 p3 = ((const float4*)(sB + (rg * 4 + 3) * XST))[j];
            o0 += w.x * p0.x + w.y * p0.y + w.z * p0.z + w.w * p0.w;
            o1 += w.x * p1.x + w.y * p1.y + w.z * p1.z + w.w * p1.w;
            o2 += w.x * p2.x + w.y * p2.y + w.z * p2.z + w.w * p2.w;
            o3 += w.x * p3.x + w.y * p3.y + w.z * p3.z + w.w * p3.w;
        }
        float bgd = bg[d];
#pragma unroll
        for (int k = 0; k < 4; k++) {
            int rr = rg * 4 + k;
            float hg = (k == 0) ? o0 : (k == 1) ? o1 : (k == 2) ? o2 : o3;
            int r = rb + rr;
            g_hg[r * DD + d] = hg;
            float dis = g_dis[r];
            out[r * DD + d] = bgd + dis * dis * hg;
        }
    }
}

// ---------------- launches 6/7: GCN edges + PReLU ----------------
__global__ void k_gcn_edges(const int* __restrict__ src, const int* __restrict__ dst,
                            int E, float* __restrict__ out) {
    int tid = blockIdx.x * blockDim.x + threadIdx.x;
    int e = tid >> 5, lane = tid & 31;
    if (e < E) {
        int s = src[e], d = dst[e];
        float norm = g_dis[s] * g_dis[d];
        float4 hv = ((const float4*)g_hg)[s * 32 + lane];
        float* ob = out + d * DD + lane * 4;
        atomicAdd(ob + 0, norm * hv.x);
        atomicAdd(ob + 1, norm * hv.y);
        atomicAdd(ob + 2, norm * hv.z);
        atomicAdd(ob + 3, norm * hv.w);
    }
}

__global__ void k_prelu(float* __restrict__ out, const float* __restrict__ pw) {
    int i = blockIdx.x * blockDim.x + threadIdx.x;
    if (i < RNUM * DD) {
        float v = out[i];
        out[i] = (v > 0.f) ? v : pw[i & 127] * v;
    }
}

// ---------------- launch ----------------
extern "C" void kernel_launch(void* const* d_in, const int* in_sizes, int n_in,
                              void* d_out, int out_size) {
    const float* x    = (const float*)d_in[0];
    const int*   zone = (const int*)d_in[1];
    const int*   adj  = (const int*)d_in[2];
    const float* S    = (const float*)d_in[3];
    const float* Wq   = (const float*)d_in[4];
    const float* bq   = (const float*)d_in[5];
    const float* Wk   = (const float*)d_in[6];
    const float* bk   = (const float*)d_in[7];
    const float* Wv   = (const float*)d_in[8];
    const float* bv   = (const float*)d_in[9];
    const float* Wo   = (const float*)d_in[10];
    const float* bo   = (const float*)d_in[11];
    const float* Wg   = (const float*)d_in[12];
    const float* bg   = (const float*)d_in[13];
    const float* pw   = (const float*)d_in[14];
    float* out = (float*)d_out;

    int N = in_sizes[0] / DD;
    int E = in_sizes[2] / 2;
    const int* esrc = adj;
    const int* edst = adj + E;
    int NE = (N > E) ? N : E;

    k_hist<<<1 + (NE + 255) / 256, 256>>>(S, Wq, bq, zone, N, edst, E);
    k_scan<<<1 + HH, 1024>>>(Wk, bk);
    k_scatter<<<(N + 255) / 256, 256>>>(zone, N);
    k_region<<<RNUM, 256>>>(x);
    k_epi<<<RNUM / 16, 512>>>(Wv, bv, Wo, bo, Wg, bg, out);
    k_gcn_edges<<<(E * 32 + 255) / 256, 256>>>(esrc, edst, E, out);
    k_prelu<<<(RNUM * DD + 255) / 256, 256>>>(out, pw);
}

// round 12
// speedup vs baseline: 1.1058x; 1.1058x over previous
#include <cuda_runtime.h>
#include <math_constants.h>

#define DD   128
#define HH   4
#define RNUM 2000
#define MAXM 768
#define NCPY 32
#define XST  132
#define CH   32

// ---------------- scratch ----------------
__device__ float  g_a[HH * DD];
__device__ float  g_c[HH];
__device__ float  g_qf[DD];
__device__ int    g_cnt32[NCPY * RNUM];   // invariant: zero at entry (scan resets)
__device__ int    g_cur32[NCPY * RNUM];
__device__ int    g_deg[RNUM];            // invariant: zero at entry (scan resets)
__device__ int    g_starts[RNUM + 1];
__device__ float  g_dis[RNUM];
__device__ int    g_idx[1 << 20];
__device__ float  g_Px[RNUM * HH * DD];
__device__ float  g_hg[RNUM * DD];

// ---------------- launch 1: qf (block 0) + hist/deg (rest) ----------------
__global__ void k_hist(const float* __restrict__ S, const float* __restrict__ Wq,
                       const float* __restrict__ bq,
                       const int* __restrict__ zone, int N,
                       const int* __restrict__ edst, int E) {
    int t = threadIdx.x;
    if (blockIdx.x == 0) {
        __shared__ float sS[DD];
        if (t < DD) sS[t] = S[t];
        __syncthreads();
        if (t < DD) {
            const float4* wr = (const float4*)(Wq + t * DD);
            const float4* sv = (const float4*)sS;
            float s = 0.f;
#pragma unroll
            for (int j = 0; j < 32; j++) {
                float4 w = wr[j], v = sv[j];
                s += w.x * v.x + w.y * v.y + w.z * v.z + w.w * v.w;
            }
            g_qf[t] = s + bq[t];
        }
        return;
    }
    int i = (blockIdx.x - 1) * 256 + t;
    if (i < N) {
        int c = (i >> 8) & (NCPY - 1);
        atomicAdd(&g_cnt32[c * RNUM + zone[i]], 1);
    }
    if (i < E) atomicAdd(&g_deg[edst[i]], 1);
}

// ---------------- launch 2: block 0 = scan; blocks 1-4 = a/c per head ----------------
__global__ void k_scan(const float* __restrict__ Wk, const float* __restrict__ bk) {
    int t = threadIdx.x; // 1024
    if (blockIdx.x > 0) {
        int h = blockIdx.x - 1;
        __shared__ float sq[32];
        __shared__ float spart[8 * DD];
        if (t < 32) sq[t] = g_qf[h * 32 + t];
        __syncthreads();
        const float scale = 0.08838834764831845f; // 1/sqrt(128)
        int j = t & 127, part = t >> 7;
        float acc = 0.f;
#pragma unroll
        for (int k = 0; k < 4; k++) {
            int dh = part * 4 + k;
            acc += sq[dh] * Wk[(h * 32 + dh) * DD + j];
        }
        spart[part * DD + j] = acc;
        __syncthreads();
        if (t < DD) {
            float s = 0.f;
#pragma unroll
            for (int p = 0; p < 8; p++) s += spart[p * DD + t];
            g_a[h * DD + t] = s * scale;
        }
        if (t == 128) {
            float s = 0.f;
#pragma unroll
            for (int dh = 0; dh < 32; dh++) s += sq[dh] * bk[h * 32 + dh];
            g_c[h] = s * scale;
        }
        return;
    }
    __shared__ int sbuf[2][2048];
    for (int k = 0; k < 2; k++) {
        int r = t + k * 1024;
        int tot = 0;
        if (r < RNUM)
            for (int c = 0; c < NCPY; c++) tot += g_cnt32[c * RNUM + r];
        sbuf[0][r] = tot;
    }
    __syncthreads();
    int src = 0;
    for (int off = 1; off < 2048; off <<= 1) {
        for (int k = 0; k < 2; k++) {
            int i = t + k * 1024;
            int v = sbuf[src][i];
            if (i >= off) v += sbuf[src][i - off];
            sbuf[1 - src][i] = v;
        }
        __syncthreads();
        src ^= 1;
    }
    for (int k = 0; k < 2; k++) {
        int r = t + k * 1024;
        if (r <= RNUM) g_starts[r] = (r == 0) ? 0 : sbuf[src][r - 1];
        if (r < RNUM) {
            int run = (r == 0) ? 0 : sbuf[src][r - 1];
            for (int c = 0; c < NCPY; c++) {
                int v = g_cnt32[c * RNUM + r];
                g_cur32[c * RNUM + r] = run;
                run += v;
                g_cnt32[c * RNUM + r] = 0;
            }
            g_dis[r] = rsqrtf((float)(g_deg[r] + 1));
            g_deg[r] = 0;
        }
    }
}

// ---------------- launch 3: scatter ----------------
__global__ void k_scatter(const int* __restrict__ zone, int N) {
    int i = blockIdx.x * blockDim.x + threadIdx.x;
    if (i < N) {
        int z = zone[i];
        int c = (i >> 8) & (NCPY - 1);
        int pos = atomicAdd(&g_cur32[c * RNUM + z], 1);
        g_idx[pos] = i;
    }
}

// ---------------- launch 4: region — two-phase chunked, partial-split scores ----------------
__device__ __forceinline__ void cp16(void* dst_smem, const void* src_gmem) {
    unsigned d = (unsigned)__cvta_generic_to_shared(dst_smem);
    asm volatile("cp.async.ca.shared.global [%0], [%1], 16;\n" :: "r"(d), "l"(src_gmem));
}
__device__ __forceinline__ void cp_commit() {
    asm volatile("cp.async.commit_group;\n" ::: "memory");
}
__device__ __forceinline__ void cp_wait0() {
    asm volatile("cp.async.wait_group 0;\n" ::: "memory");
}

__global__ __launch_bounds__(256, 5) void k_region(const float* __restrict__ x) {
    int r = blockIdx.x;
    int base = g_starts[r];
    int cnt = g_starts[r + 1] - base;
    if (cnt > MAXM) cnt = MAXM;
    int t = threadIdx.x;

    if (cnt == 0) {
        for (int o = t; o < HH * DD; o += 256) g_Px[r * (HH * DD) + o] = 0.f;
        return;
    }

    __shared__ __align__(16) float pool[2][CH * XST];  // 33.8 KB; red aliases pool[0] at end
    __shared__ __align__(16) float saP[HH * XST];      // padded A (2.1 KB)
    __shared__ __align__(16) float sp[8 * CH * HH];    // phase-A partials (4 KB)
    __shared__ __align__(16) float se[CH * HH];        // exp-scores (0.5 KB)
    __shared__ int   sidx[MAXM];                       // 3 KB
    __shared__ float scc[HH];
    __shared__ float sden[8 * HH];
    __shared__ float sinv[HH];

    for (int i = t; i < HH * DD; i += 256) saP[(i >> 7) * XST + (i & 127)] = g_a[i];
    if (t < HH) scc[t] = g_c[t];
    for (int i = t; i < cnt; i += 256) sidx[i] = g_idx[base + i];
    __syncthreads();

    int warp = t >> 5, lane = t & 31;
    int nch = (cnt + CH - 1) / CH;

    // staging map: row = t>>3 (32 rows), part8 = t&7 (64B each), 4 x cp16
    int srow = t >> 3, spart8 = t & 7;

    // prologue: stage chunk 0
    {
        int cc = min(CH, cnt);
        if (srow < cc) {
            int n = sidx[srow];
            const float* src = x + (size_t)n * DD + spart8 * 16;
            float* dst = &pool[0][srow * XST + spart8 * 16];
#pragma unroll
            for (int q = 0; q < 4; q++) cp16(dst + q * 4, src + q * 4);
        }
        cp_commit();
    }

    // phase A mapping: m = lane (t&31), slice = warp (t>>5): 16 floats per slice
    int am = lane, apart = warp;
    // combine mapping (t < 128): m2 = t>>2, h2 = t&3
    int m2 = t >> 2, h2 = t & 3;
    float c2 = scc[h2];

    float4 acc0 = make_float4(0.f, 0.f, 0.f, 0.f), acc1 = acc0, acc2 = acc0, acc3 = acc0;
    float den0 = 0.f, den1 = 0.f, den2 = 0.f, den3 = 0.f;

    for (int c = 0; c < nch; c++) {
        int buf = c & 1;
        int cc = min(CH, cnt - c * CH);
        cp_wait0();
        __syncthreads();   // chunk c ready; previous phase B complete

        // stage chunk c+1 into the other buffer
        if (c + 1 < nch) {
            int cc1 = min(CH, cnt - (c + 1) * CH);
            if (srow < cc1) {
                int n = sidx[(c + 1) * CH + srow];
                const float* src = x + (size_t)n * DD + spart8 * 16;
                float* dst = &pool[buf ^ 1][srow * XST + spart8 * 16];
#pragma unroll
                for (int q = 0; q < 4; q++) cp16(dst + q * 4, src + q * 4);
            }
        }
        cp_commit();

        // ---- phase A: partial dots; thread = (member am, 16-float slice apart) ----
        if (am < cc) {
            const float4* xr = (const float4*)(pool[buf] + am * XST + apart * 16);
            const float4* a0 = (const float4*)(saP + 0 * XST + apart * 16);
            const float4* a1 = (const float4*)(saP + 1 * XST + apart * 16);
            const float4* a2 = (const float4*)(saP + 2 * XST + apart * 16);
            const float4* a3 = (const float4*)(saP + 3 * XST + apart * 16);
            float p0 = 0.f, p1 = 0.f, p2 = 0.f, p3 = 0.f;
#pragma unroll
            for (int k = 0; k < 4; k++) {
                float4 xv = xr[k];
                float4 v0 = a0[k], v1 = a1[k], v2 = a2[k], v3 = a3[k];  // warp-uniform (broadcast)
                p0 += xv.x * v0.x + xv.y * v0.y + xv.z * v0.z + xv.w * v0.w;
                p1 += xv.x * v1.x + xv.y * v1.y + xv.z * v1.z + xv.w * v1.w;
                p2 += xv.x * v2.x + xv.y * v2.y + xv.z * v2.z + xv.w * v2.w;
                p3 += xv.x * v3.x + xv.y * v3.y + xv.z * v3.z + xv.w * v3.w;
            }
            *(float4*)&sp[apart * (CH * HH) + am * 4] = make_float4(p0, p1, p2, p3);
        }
        __syncthreads();

        // ---- combine: 128 threads sum 8 partials + expf ----
        if (t < 128 && m2 < cc) {
            float s = 0.f;
#pragma unroll
            for (int p = 0; p < 8; p++) s += sp[p * (CH * HH) + m2 * 4 + h2];
            se[m2 * 4 + h2] = __expf(s + c2);
        }
        __syncthreads();

        // ---- phase B: accumulate, warp-per-member-stride ----
        for (int i = warp; i < cc; i += 8) {
            float4 ev = *(const float4*)(se + i * HH);                 // broadcast
            float4 xv = *(const float4*)(pool[buf] + i * XST + lane * 4);
            acc0.x += ev.x * xv.x; acc0.y += ev.x * xv.y; acc0.z += ev.x * xv.z; acc0.w += ev.x * xv.w;
            acc1.x += ev.y * xv.x; acc1.y += ev.y * xv.y; acc1.z += ev.y * xv.z; acc1.w += ev.y * xv.w;
            acc2.x += ev.z * xv.x; acc2.y += ev.z * xv.y; acc2.z += ev.z * xv.z; acc2.w += ev.z * xv.w;
            acc3.x += ev.w * xv.x; acc3.y += ev.w * xv.y; acc3.z += ev.w * xv.z; acc3.w += ev.w * xv.w;
            den0 += ev.x; den1 += ev.y; den2 += ev.z; den3 += ev.w;
        }
    }
    __syncthreads();   // all phase B done; pool now dead -> alias as reduction buffer

    float* red = pool[0];   // 8 * HH * DD = 16 KB <= 16.9 KB
    ((float4*)(red + (warp * HH + 0) * DD))[lane] = acc0;
    ((float4*)(red + (warp * HH + 1) * DD))[lane] = acc1;
    ((float4*)(red + (warp * HH + 2) * DD))[lane] = acc2;
    ((float4*)(red + (warp * HH + 3) * DD))[lane] = acc3;
    if (lane == 0) {
        sden[warp * HH + 0] = den0; sden[warp * HH + 1] = den1;
        sden[warp * HH + 2] = den2; sden[warp * HH + 3] = den3;
    }
    __syncthreads();
    if (t < HH) {
        float s = 0.f;
#pragma unroll
        for (int g = 0; g < 8; g++) s += sden[g * HH + t];
        sinv[t] = 1.f / s;
    }
    __syncthreads();
    for (int o = t; o < HH * DD; o += 256) {
        int hh = o >> 7, d = o & 127;
        float s = 0.f;
#pragma unroll
        for (int g = 0; g < 8; g++) s += red[(g * HH + hh) * DD + d];
        g_Px[r * (HH * DD) + o] = s * sinv[hh];
    }
}

// ---------------- launch 5: fused dense epilogue ----------------
__global__ __launch_bounds__(512) void k_epi(
    const float* __restrict__ Wv, const float* __restrict__ bv,
    const float* __restrict__ Wo, const float* __restrict__ bo,
    const float* __restrict__ Wg, const float* __restrict__ bg,
    float* __restrict__ out) {
    int rb = blockIdx.x * 16;
    __shared__ __align__(16) float sPx[16 * 512];
    __shared__ __align__(16) float sA[16 * XST];
    __shared__ __align__(16) float sB[16 * XST];
    __shared__ float sqf[DD];
    __shared__ float sflag[16];
    int t = threadIdx.x;

    for (int i = t; i < 16 * 512; i += 512) sPx[i] = g_Px[rb * 512 + i];
    if (t < DD) sqf[t] = g_qf[t];
    if (t < 16) sflag[t] = (g_starts[rb + t + 1] > g_starts[rb + t]) ? 1.f : 0.f;
    __syncthreads();

    int d = t & 127, rg = t >> 7;
    int h = d >> 5;
    {
        const float4* wv4 = (const float4*)(Wv + d * DD);
        float o0 = 0.f, o1 = 0.f, o2 = 0.f, o3 = 0.f;
#pragma unroll 8
        for (int j = 0; j < 32; j++) {
            float4 w = wv4[j];
            float4 p0 = ((const float4*)(sPx + (rg * 4 + 0) * 512 + h * DD))[j];
            float4 p1 = ((const float4*)(sPx + (rg * 4 + 1) * 512 + h * DD))[j];
            float4 p2 = ((const float4*)(sPx + (rg * 4 + 2) * 512 + h * DD))[j];
            float4 p3 = ((const float4*)(sPx + (rg * 4 + 3) * 512 + h * DD))[j];
            o0 += w.x * p0.x + w.y * p0.y + w.z * p0.z + w.w * p0.w;
            o1 += w.x * p1.x + w.y * p1.y + w.z * p1.z + w.w * p1.w;
            o2 += w.x * p2.x + w.y * p2.y + w.z * p2.z + w.w * p2.w;
            o3 += w.x * p3.x + w.y * p3.y + w.z * p3.z + w.w * p3.w;
        }
        float bvd = bv[d], qfd = sqf[d];
        sA[(rg * 4 + 0) * XST + d] = qfd + (o0 + bvd) * sflag[rg * 4 + 0];
        sA[(rg * 4 + 1) * XST + d] = qfd + (o1 + bvd) * sflag[rg * 4 + 1];
        sA[(rg * 4 + 2) * XST + d] = qfd + (o2 + bvd) * sflag[rg * 4 + 2];
        sA[(rg * 4 + 3) * XST + d] = qfd + (o3 + bvd) * sflag[rg * 4 + 3];
    }
    __syncthreads();
    {
        const float4* wo4 = (const float4*)(Wo + d * DD);
        float o0 = 0.f, o1 = 0.f, o2 = 0.f, o3 = 0.f;
#pragma unroll 8
        for (int j = 0; j < 32; j++) {
            float4 w = wo4[j];
            float4 p0 = ((const float4*)(sA + (rg * 4 + 0) * XST))[j];
            float4 p1 = ((const float4*)(sA + (rg * 4 + 1) * XST))[j];
            float4 p2 = ((const float4*)(sA + (rg * 4 + 2) * XST))[j];
            float4 p3 = ((const float4*)(sA + (rg * 4 + 3) * XST))[j];
            o0 += w.x * p0.x + w.y * p0.y + w.z * p0.z + w.w * p0.w;
            o1 += w.x * p1.x + w.y * p1.y + w.z * p1.z + w.w * p1.w;
            o2 += w.x * p2.x + w.y * p2.y + w.z * p2.z + w.w * p2.w;
            o3 += w.x * p3.x + w.y * p3.y + w.z * p3.z + w.w * p3.w;
        }
        float bod = bo[d];
        sB[(rg * 4 + 0) * XST + d] = sA[(rg * 4 + 0) * XST + d] + fmaxf(o0 + bod, 0.f);
        sB[(rg * 4 + 1) * XST + d] = sA[(rg * 4 + 1) * XST + d] + fmaxf(o1 + bod, 0.f);
        sB[(rg * 4 + 2) * XST + d] = sA[(rg * 4 + 2) * XST + d] + fmaxf(o2 + bod, 0.f);
        sB[(rg * 4 + 3) * XST + d] = sA[(rg * 4 + 3) * XST + d] + fmaxf(o3 + bod, 0.f);
    }
    __syncthreads();
    {
        const float4* wg4 = (const float4*)(Wg + d * DD);
        float o0 = 0.f, o1 = 0.f, o2 = 0.f, o3 = 0.f;
#pragma unroll 8
        for (int j = 0; j < 32; j++) {
            float4 w = wg4[j];
            float4 p0 = ((const float4*)(sB + (rg * 4 + 0) * XST))[j];
            float4 p1 = ((const float4*)(sB + (rg * 4 + 1) * XST))[j];
            float4 p2 = ((const float4*)(sB + (rg * 4 + 2) * XST))[j];
            float4 p3 = ((const float4*)(sB + (rg * 4 + 3) * XST))[j];
            o0 += w.x * p0.x + w.y * p0.y + w.z * p0.z + w.w * p0.w;
            o1 += w.x * p1.x + w.y * p1.y + w.z * p1.z + w.w * p1.w;
            o2 += w.x * p2.x + w.y * p2.y + w.z * p2.z + w.w * p2.w;
            o3 += w.x * p3.x + w.y * p3.y + w.z * p3.z + w.w * p3.w;
        }
        float bgd = bg[d];
#pragma unroll
        for (int k = 0; k < 4; k++) {
            int rr = rg * 4 + k;
            float hg = (k == 0) ? o0 : (k == 1) ? o1 : (k == 2) ? o2 : o3;
            int r = rb + rr;
            g_hg[r * DD + d] = hg;
            float dis = g_dis[r];
            out[r * DD + d] = bgd + dis * dis * hg;
        }
    }
}

// ---------------- launches 6/7: GCN edges + PReLU ----------------
__global__ void k_gcn_edges(const int* __restrict__ src, const int* __restrict__ dst,
                            int E, float* __restrict__ out) {
    int tid = blockIdx.x * blockDim.x + threadIdx.x;
    int e = tid >> 5, lane = tid & 31;
    if (e < E) {
        int s = src[e], d = dst[e];
        float norm = g_dis[s] * g_dis[d];
        float4 hv = ((const float4*)g_hg)[s * 32 + lane];
        float* ob = out + d * DD + lane * 4;
        atomicAdd(ob + 0, norm * hv.x);
        atomicAdd(ob + 1, norm * hv.y);
        atomicAdd(ob + 2, norm * hv.z);
        atomicAdd(ob + 3, norm * hv.w);
    }
}

__global__ void k_prelu(float* __restrict__ out, const float* __restrict__ pw) {
    int i = blockIdx.x * blockDim.x + threadIdx.x;
    if (i < RNUM * DD) {
        float v = out[i];
        out[i] = (v > 0.f) ? v : pw[i & 127] * v;
    }
}

// ---------------- launch ----------------
extern "C" void kernel_launch(void* const* d_in, const int* in_sizes, int n_in,
                              void* d_out, int out_size) {
    const float* x    = (const float*)d_in[0];
    const int*   zone = (const int*)d_in[1];
    const int*   adj  = (const int*)d_in[2];
    const float* S    = (const float*)d_in[3];
    const float* Wq   = (const float*)d_in[4];
    const float* bq   = (const float*)d_in[5];
    const float* Wk   = (const float*)d_in[6];
    const float* bk   = (const float*)d_in[7];
    const float* Wv   = (const float*)d_in[8];
    const float* bv   = (const float*)d_in[9];
    const float* Wo   = (const float*)d_in[10];
    const float* bo   = (const float*)d_in[11];
    const float* Wg   = (const float*)d_in[12];
    const float* bg   = (const float*)d_in[13];
    const float* pw   = (const float*)d_in[14];
    float* out = (float*)d_out;

    int N = in_sizes[0] / DD;
    int E = in_sizes[2] / 2;
    const int* esrc = adj;
    const int* edst = adj + E;
    int NE = (N > E) ? N : E;

    k_hist<<<1 + (NE + 255) / 256, 256>>>(S, Wq, bq, zone, N, edst, E);
    k_scan<<<1 + HH, 1024>>>(Wk, bk);
    k_scatter<<<(N + 255) / 256, 256>>>(zone, N);
    k_region<<<RNUM, 256>>>(x);
    k_epi<<<RNUM / 16, 512>>>(Wv, bv, Wo, bo, Wg, bg, out);
    k_gcn_edges<<<(E * 32 + 255) / 256, 256>>>(esrc, edst, E, out);
    k_prelu<<<(RNUM * DD + 255) / 256, 256>>>(out, pw);
}